// round 13
// baseline (speedup 1.0000x reference)
#include <cuda_runtime.h>
#include <cuda_fp16.h>
#include <math.h>

// Problem constants
#define PB 16      // batch
#define PS 4096    // sequence
#define PD 64      // head dim
#define PH 8       // n_hashes
#define PNB 64     // n_buckets
#define PCHUNKS 512 // chunks per batch (PH * PNB), each of 64 tokens

typedef unsigned long long u64;

// ---- packed fp32x2 helpers (Blackwell FFMA2 path) -------------------------
__device__ __forceinline__ u64 pack2(float x, float y) {
    u64 r; asm("mov.b64 %0, {%1, %2};" : "=l"(r) : "f"(x), "f"(y)); return r;
}
__device__ __forceinline__ float2 unpack2(u64 p) {
    float2 v; asm("mov.b64 {%0, %1}, %2;" : "=f"(v.x), "=f"(v.y) : "l"(p)); return v;
}
__device__ __forceinline__ u64 ffma2(u64 a, u64 b, u64 c) {
    asm("fma.rn.f32x2 %0, %1, %2, %0;" : "+l"(c) : "l"(a), "l"(b));
    return c;
}

// ---------------- scratch (device globals; no allocation allowed) ----------
__device__ unsigned char g_bucket[PB * PH * PS];            // 512 KB
__device__ int           g_st[PB * PH * PS];                // 2 MB   sorted pos -> original t
__device__ float         g_lse[PB * PH * PS];               // 2 MB   [b][h][t]
__device__ __half        g_o[(size_t)PB * PH * PS * PD];    // 64 MB  [b][h][t][d] fp16

// ---------------------------------------------------------------------------
// Kernel 1: hashing. rotated[i] = sum_f qk[b,t,f] * rot[f,h,i]; argmax over
// [rotated, -rotated] with first-occurrence tie-breaking (match jnp.argmax).
// ---------------------------------------------------------------------------
__global__ void __launch_bounds__(256) k_hash(
    const float* __restrict__ qk, const float* __restrict__ rot,
    float* __restrict__ out_tail, int write_buckets)
{
    __shared__ float rot_s[64 * 32];   // rotations for one hash round: [f][i]
    int b = blockIdx.x >> 4;
    int t = ((blockIdx.x & 15) << 8) + threadIdx.x;

    const float* qr = qk + ((size_t)b * PS + t) * PD;
    float q[64];
#pragma unroll
    for (int f4 = 0; f4 < 16; f4++) {
        float4 v4 = ((const float4*)qr)[f4];
        q[f4 * 4 + 0] = v4.x; q[f4 * 4 + 1] = v4.y;
        q[f4 * 4 + 2] = v4.z; q[f4 * 4 + 3] = v4.w;
    }

    for (int h = 0; h < PH; h++) {
        __syncthreads();
        for (int e = threadIdx.x; e < 2048; e += 256) {
            int f = e >> 5, i = e & 31;
            rot_s[e] = rot[f * 256 + h * 32 + i];  // rot layout [f][h][i] (b bcast)
        }
        __syncthreads();

        u64 acc[16];
#pragma unroll
        for (int p = 0; p < 16; p++) acc[p] = 0ull;   // (0.0f, 0.0f)

        for (int f = 0; f < 64; f++) {
            u64 qb = pack2(q[f], q[f]);
            const ulonglong2* rr = (const ulonglong2*)&rot_s[f * 32]; // LDS.128 bcast
#pragma unroll
            for (int p2 = 0; p2 < 8; p2++) {
                ulonglong2 vv = rr[p2];
                acc[2 * p2 + 0] = ffma2(qb, vv.x, acc[2 * p2 + 0]);
                acc[2 * p2 + 1] = ffma2(qb, vv.y, acc[2 * p2 + 1]);
            }
        }

        float bestp = -1e30f, bestn = -1e30f;
        int ip = 0, inn = 0;
#pragma unroll
        for (int p = 0; p < 16; p++) {
            float2 a = unpack2(acc[p]);
            int i0 = 2 * p, i1 = 2 * p + 1;
            if ( a.x > bestp) { bestp =  a.x; ip  = i0; }
            if (-a.x > bestn) { bestn = -a.x; inn = i0; }
            if ( a.y > bestp) { bestp =  a.y; ip  = i1; }
            if (-a.y > bestn) { bestn = -a.y; inn = i1; }
        }
        int idx = (bestp >= bestn) ? ip : (32 + inn);  // plus-half wins ties
        g_bucket[((size_t)b * PH + h) * PS + t] = (unsigned char)idx;
        if (write_buckets)
            out_tail[((size_t)b * PH + h) * PS + t] = (float)(idx + h * PNB);
    }
}

// ---------------------------------------------------------------------------
// Kernel 2: stable counting sort per (b,h): 4096 tokens into 64 buckets by
// (bucket, t) — exactly jnp.argsort of S*bucket + t. grid: PB*PH, 128 threads.
// ---------------------------------------------------------------------------
__global__ void __launch_bounds__(128) k_sort()
{
    __shared__ unsigned char sb[4096];
    __shared__ int hist[64];
    __shared__ int offs[64];
    int bh = blockIdx.x;
    int tid = threadIdx.x;

    if (tid < 64) hist[tid] = 0;
    const unsigned int* src = (const unsigned int*)(g_bucket + (size_t)bh * PS);
    unsigned int* dstb = (unsigned int*)sb;
    for (int i = tid; i < 1024; i += 128) dstb[i] = src[i];
    __syncthreads();

    for (int t = tid; t < 4096; t += 128) atomicAdd(&hist[sb[t]], 1);
    __syncthreads();

    if (tid == 0) {
        int run = 0;
        for (int k = 0; k < 64; k++) { offs[k] = run; run += hist[k]; }
    }
    __syncthreads();

    if (tid < 64) {
        int k = tid;
        int pos = offs[k];
        int* dst = g_st + (size_t)bh * PS;
        for (int t = 0; t < 4096; t++)
            if (sb[t] == (unsigned char)k) dst[pos++] = t;  // stable: t ascending
    }
}

// ---------------------------------------------------------------------------
// Kernel 3: chunk attention, 128 threads/CTA, big register tiles to cut LDS:
//   QK^T: 8x8 tile per thread (ty=tid>>4 rows 8ty..8ty+7; tx=tid&15 cols
//   8tx..8tx+7 as 4 FFMA2 pairs). K^T stride 132 so the 8-wide col block is
//   two aligned LDS.128 (ulonglong2 = ready packed operands).
//   Register softmax (16-lane shfl), 1/s stashed in s_inv[64].
//   PV: remap ry=tid>>3 (rows ry+16ii), tx8=tid&7 (d=8tx8..+7), V via
//   aligned LDS.128 pairs. fp16 scatter by st (fused unsort).
// ---------------------------------------------------------------------------
#define SM_Q   (64 * 68)     // 4352 floats (row stride 68 -> 272B, 16B-aligned)
#define SM_KV  (64 * 132)    // 8448 floats (K^T stride 132; reused for V [128][64])
#define SM_DOT (64 * 132)    // 8448 floats (P stride 132)
#define SMEM3_FLOATS (SM_Q + SM_KV + SM_DOT + 128 + 64)
#define SMEM3_BYTES  (SMEM3_FLOATS * 4)

__global__ void __launch_bounds__(128) k_attn(
    const float* __restrict__ qk, const float* __restrict__ v)
{
    extern __shared__ float sm[];
    float* q_s   = sm;                        // [i*68 + f]
    float* kv_s  = sm + SM_Q;                 // K^T: [f*132 + j]; later V: [j*64 + d]
    float* p_s   = sm + SM_Q + SM_KV;         // P: [i*132 + j]
    int*   st_k  = (int*)(p_s + SM_DOT);      // 128 orig positions
    float* s_inv = (float*)(st_k + 128);      // 64 per-row 1/sum

    int tid = threadIdx.x;
    int b = blockIdx.x >> 9;
    int c = blockIdx.x & 511;
    int h  = c >> 6;
    int cp = (c + 511) & 511;
    int hp = cp >> 6;

    if (tid < 64) {
        st_k[tid]      = g_st[((size_t)b * PH + h ) * PS + (c  & 63) * 64 + tid];
        st_k[64 + tid] = g_st[((size_t)b * PH + hp) * PS + (cp & 63) * 64 + tid];
    }
    __syncthreads();

    // ---- load Q (raw): threads 0-63 cover f 0..31, 64-127 cover f 32..63 --
    {
        int i  = tid & 63;
        int f0 = (tid >> 6) * 32;
        const float* row = qk + ((size_t)b * PS + st_k[i]) * PD + f0;
        float* dst = q_s + i * 68 + f0;
#pragma unroll
        for (int u = 0; u < 8; u++) {
            float4 v4 = ((const float4*)row)[u];
            ((float4*)dst)[u] = v4;
        }
    }
    // ---- load K: row-normalized (clip 1e-12), transposed, stride 132 ----
    {
        int j = tid;
        const float* row = qk + ((size_t)b * PS + st_k[j]) * PD;
        float r[64];
        float ss = 0.f;
#pragma unroll
        for (int u = 0; u < 16; u++) {
            float4 v4 = ((const float4*)row)[u];
            r[u * 4 + 0] = v4.x; r[u * 4 + 1] = v4.y;
            r[u * 4 + 2] = v4.z; r[u * 4 + 3] = v4.w;
            ss += v4.x * v4.x + v4.y * v4.y + v4.z * v4.z + v4.w * v4.w;
        }
        float inv = 1.0f / fmaxf(sqrtf(ss), 1e-12f);
#pragma unroll
        for (int f = 0; f < 64; f++) kv_s[f * 132 + j] = r[f] * inv;
    }
    __syncthreads();

    int ty = tid >> 4, tx = tid & 15;    // QK^T map: rows 8ty+ii, cols 8tx+u

    // ---- dots = Q K^T (FFMA2, 8x8 tile, aligned LDS.128 both operands) ----
    {
        u64 acc[8][4];
#pragma unroll
        for (int ii = 0; ii < 8; ii++)
#pragma unroll
            for (int g = 0; g < 4; g++) acc[ii][g] = 0ull;

        for (int kk0 = 0; kk0 < 64; kk0 += 4) {
            float4 qv[8];
#pragma unroll
            for (int ii = 0; ii < 8; ii++)
                qv[ii] = *(const float4*)&q_s[(8 * ty + ii) * 68 + kk0]; // LDS.128
#pragma unroll
            for (int u = 0; u < 4; u++) {
                int kk = kk0 + u;
                ulonglong2 k01 = *(const ulonglong2*)&kv_s[kk * 132 + 8 * tx];     // LDS.128
                ulonglong2 k23 = *(const ulonglong2*)&kv_s[kk * 132 + 8 * tx + 4]; // LDS.128
#pragma unroll
                for (int ii = 0; ii < 8; ii++) {
                    float qf = (u == 0) ? qv[ii].x : (u == 1) ? qv[ii].y
                             : (u == 2) ? qv[ii].z : qv[ii].w;
                    u64 qb = pack2(qf, qf);
                    acc[ii][0] = ffma2(qb, k01.x, acc[ii][0]);
                    acc[ii][1] = ffma2(qb, k01.y, acc[ii][1]);
                    acc[ii][2] = ffma2(qb, k23.x, acc[ii][2]);
                    acc[ii][3] = ffma2(qb, k23.y, acc[ii][3]);
                }
            }
        }

        // ---- scale + self-mask + register softmax (16-lane shfl rows) ----
        int tj[8];
#pragma unroll
        for (int u = 0; u < 8; u++) tj[u] = st_k[8 * tx + u];

#pragma unroll
        for (int ii = 0; ii < 8; ii++) {
            int i = 8 * ty + ii;
            int ti = st_k[i];
            float2 p[4];
#pragma unroll
            for (int g = 0; g < 4; g++) {
                p[g] = unpack2(acc[ii][g]);
                p[g].x *= 0.125f; p[g].y *= 0.125f;
                if (ti == tj[2 * g])     p[g].x = -1e5f;
                if (ti == tj[2 * g + 1]) p[g].y = -1e5f;
            }
            float m = fmaxf(fmaxf(fmaxf(p[0].x, p[0].y), fmaxf(p[1].x, p[1].y)),
                            fmaxf(fmaxf(p[2].x, p[2].y), fmaxf(p[3].x, p[3].y)));
            m = fmaxf(m, __shfl_xor_sync(0xffffffffu, m, 1));
            m = fmaxf(m, __shfl_xor_sync(0xffffffffu, m, 2));
            m = fmaxf(m, __shfl_xor_sync(0xffffffffu, m, 4));
            m = fmaxf(m, __shfl_xor_sync(0xffffffffu, m, 8));
            float s = 0.f;
#pragma unroll
            for (int g = 0; g < 4; g++) {
                p[g].x = __expf(p[g].x - m);
                p[g].y = __expf(p[g].y - m);
                s += p[g].x + p[g].y;
            }
            s += __shfl_xor_sync(0xffffffffu, s, 1);
            s += __shfl_xor_sync(0xffffffffu, s, 2);
            s += __shfl_xor_sync(0xffffffffu, s, 4);
            s += __shfl_xor_sync(0xffffffffu, s, 8);
            // write unnormalized P once (two STS.128 per row per thread)
            float4* dst = (float4*)&p_s[i * 132 + 8 * tx];
            dst[0] = make_float4(p[0].x, p[0].y, p[1].x, p[1].y);
            dst[1] = make_float4(p[2].x, p[2].y, p[3].x, p[3].y);
            if (tx == 0) {
                g_lse[((size_t)b * PH + h) * PS + ti] = m + __logf(s);
                s_inv[i] = 1.0f / s;
            }
        }
    }
    __syncthreads();   // all Q/K^T reads done -> safe to overwrite kv_s with V

    // ---- load V into kv_s: one row per thread ----
    {
        int j = tid;
        const float* row = v + ((size_t)b * PS + st_k[j]) * PD;
        float* dv = kv_s + j * 64;
#pragma unroll
        for (int u = 0; u < 16; u++)
            ((float4*)dv)[u] = ((const float4*)row)[u];
    }
    __syncthreads();

    // ---- O = P V (FFMA2; rows ry+16ii, d = 8tx8..+7), scale, fp16 scatter --
    {
        int ry = tid >> 3, tx8 = tid & 7;
        u64 oacc[4][4];
#pragma unroll
        for (int ii = 0; ii < 4; ii++)
#pragma unroll
            for (int g = 0; g < 4; g++) oacc[ii][g] = 0ull;

        for (int j0 = 0; j0 < 128; j0 += 4) {
            float4 pv4[4];
#pragma unroll
            for (int ii = 0; ii < 4; ii++)
                pv4[ii] = *(const float4*)&p_s[(ry + 16 * ii) * 132 + j0]; // LDS.128
#pragma unroll
            for (int u = 0; u < 4; u++) {
                int j = j0 + u;
                ulonglong2 v01 = *(const ulonglong2*)&kv_s[j * 64 + 8 * tx8];     // LDS.128
                ulonglong2 v23 = *(const ulonglong2*)&kv_s[j * 64 + 8 * tx8 + 4]; // LDS.128
#pragma unroll
                for (int ii = 0; ii < 4; ii++) {
                    float pf = (u == 0) ? pv4[ii].x : (u == 1) ? pv4[ii].y
                             : (u == 2) ? pv4[ii].z : pv4[ii].w;
                    u64 pb = pack2(pf, pf);
                    oacc[ii][0] = ffma2(pb, v01.x, oacc[ii][0]);
                    oacc[ii][1] = ffma2(pb, v01.y, oacc[ii][1]);
                    oacc[ii][2] = ffma2(pb, v23.x, oacc[ii][2]);
                    oacc[ii][3] = ffma2(pb, v23.y, oacc[ii][3]);
                }
            }
        }
#pragma unroll
        for (int ii = 0; ii < 4; ii++) {
            int i = ry + 16 * ii;
            float inv = s_inv[i];
            size_t base = (((size_t)b * PH + h) * PS + st_k[i]) * (size_t)PD;
            __half2 hh[4];
#pragma unroll
            for (int g = 0; g < 4; g++) {
                float2 a = unpack2(oacc[ii][g]);
                hh[g] = __floats2half2_rn(a.x * inv, a.y * inv);
            }
            uint4 packed = make_uint4(*(unsigned*)&hh[0], *(unsigned*)&hh[1],
                                      *(unsigned*)&hh[2], *(unsigned*)&hh[3]);
            *(uint4*)&g_o[base + 8 * tx8] = packed;   // STG.128, coalesced
        }
    }
}

// ---------------------------------------------------------------------------
// no-op launch: keeps the fixed ncu capture slot (our 4th launch) on k_attn
// ---------------------------------------------------------------------------
__global__ void k_nop() {}

// ---------------------------------------------------------------------------
// Kernel 4: combine hash rounds: w_h = exp(lse_h - logsumexp_h), out = sum w_h o_h.
// fp16 g_o read as half2 pairs; fp32 accumulate + output.
// ---------------------------------------------------------------------------
__global__ void __launch_bounds__(256) k_combine(float* __restrict__ out)
{
    __shared__ float sw[32 * 8];
    int b  = blockIdx.x >> 7;
    int t0 = (blockIdx.x & 127) * 32;
    int tid = threadIdx.x;
    int tl = tid >> 3, h = tid & 7;
    int t = t0 + tl;

    float l = g_lse[((size_t)b * PH + h) * PS + t];
    float m = l;
#pragma unroll
    for (int o = 4; o; o >>= 1) m = fmaxf(m, __shfl_xor_sync(0xffffffffu, m, o));
    float s = __expf(l - m);
#pragma unroll
    for (int o = 4; o; o >>= 1) s += __shfl_xor_sync(0xffffffffu, s, o);
    sw[tl * 8 + h] = __expf(l - (m + __logf(s)));
    __syncthreads();

    // 32 tokens x 32 d-pairs = 1024 pairs, 4 per thread
#pragma unroll
    for (int r = 0; r < 4; r++) {
        int idx = tid + r * 256;
        int tl2 = idx >> 5, dp = idx & 31;
        int t2 = t0 + tl2;
        float ax = 0.f, ay = 0.f;
#pragma unroll
        for (int hh = 0; hh < 8; hh++) {
            __half2 hv = *(const __half2*)
                &g_o[(((size_t)b * PH + hh) * PS + t2) * (size_t)PD + 2 * dp];
            float2 f = __half22float2(hv);
            float w = sw[tl2 * 8 + hh];
            ax += f.x * w; ay += f.y * w;
        }
        float2 res = make_float2(ax, ay);
        *(float2*)&out[((size_t)b * PS + t2) * (size_t)PD + 2 * dp] = res;
    }
}

// ---------------------------------------------------------------------------
extern "C" void kernel_launch(void* const* d_in, const int* in_sizes, int n_in,
                              void* d_out, int out_size)
{
    (void)n_in; (void)in_sizes;
    const float* qk  = (const float*)d_in[0];
    const float* v   = (const float*)d_in[1];
    const float* rot = (const float*)d_in[2];
    float* out = (float*)d_out;

    const int n_main = PB * PS * PD;            // 4194304
    const int n_buck = PB * PH * PS;            // 524288
    int write_buckets = (out_size >= n_main + n_buck) ? 1 : 0;

    cudaFuncSetAttribute(k_attn, cudaFuncAttributeMaxDynamicSharedMemorySize,
                         SMEM3_BYTES);

    k_hash<<<PB * (PS / 256), 256>>>(qk, rot, out + n_main, write_buckets);
    k_sort<<<PB * PH, 128>>>();
    k_nop<<<1, 32>>>();   // capture slot #4 (2 harness launches + these) = k_attn
    k_attn<<<PB * PCHUNKS, 128, SMEM3_BYTES>>>(qk, v);
    k_combine<<<PB * (PS / 32), 256>>>(out);
}

// round 14
// speedup vs baseline: 1.3587x; 1.3587x over previous
#include <cuda_runtime.h>
#include <cuda_fp16.h>
#include <math.h>

// Problem constants
#define PB 16      // batch
#define PS 4096    // sequence
#define PD 64      // head dim
#define PH 8       // n_hashes
#define PNB 64     // n_buckets
#define PCHUNKS 512 // chunks per batch (PH * PNB), each of 64 tokens

typedef unsigned long long u64;

// ---- packed fp32x2 helpers (Blackwell FFMA2 path) -------------------------
__device__ __forceinline__ u64 pack2(float x, float y) {
    u64 r; asm("mov.b64 %0, {%1, %2};" : "=l"(r) : "f"(x), "f"(y)); return r;
}
__device__ __forceinline__ float2 unpack2(u64 p) {
    float2 v; asm("mov.b64 {%0, %1}, %2;" : "=f"(v.x), "=f"(v.y) : "l"(p)); return v;
}
__device__ __forceinline__ u64 ffma2(u64 a, u64 b, u64 c) {
    asm("fma.rn.f32x2 %0, %1, %2, %0;" : "+l"(c) : "l"(a), "l"(b));
    return c;
}

// ---------------- scratch (device globals; no allocation allowed) ----------
__device__ unsigned char g_bucket[PB * PH * PS];            // 512 KB
__device__ int           g_st[PB * PH * PS];                // 2 MB   sorted pos -> original t
__device__ float         g_lse[PB * PH * PS];               // 2 MB   [b][h][t]
__device__ __half        g_o[(size_t)PB * PH * PS * PD];    // 64 MB  [b][h][t][d] fp16

// ---------------------------------------------------------------------------
// Kernel 1: hashing. rotated[i] = sum_f qk[b,t,f] * rot[f,h,i]; argmax over
// [rotated, -rotated] with first-occurrence tie-breaking (match jnp.argmax).
// ---------------------------------------------------------------------------
__global__ void __launch_bounds__(256) k_hash(
    const float* __restrict__ qk, const float* __restrict__ rot,
    float* __restrict__ out_tail, int write_buckets)
{
    __shared__ float rot_s[64 * 32];   // rotations for one hash round: [f][i]
    int b = blockIdx.x >> 4;
    int t = ((blockIdx.x & 15) << 8) + threadIdx.x;

    const float* qr = qk + ((size_t)b * PS + t) * PD;
    float q[64];
#pragma unroll
    for (int f4 = 0; f4 < 16; f4++) {
        float4 v4 = ((const float4*)qr)[f4];
        q[f4 * 4 + 0] = v4.x; q[f4 * 4 + 1] = v4.y;
        q[f4 * 4 + 2] = v4.z; q[f4 * 4 + 3] = v4.w;
    }

    for (int h = 0; h < PH; h++) {
        __syncthreads();
        for (int e = threadIdx.x; e < 2048; e += 256) {
            int f = e >> 5, i = e & 31;
            rot_s[e] = rot[f * 256 + h * 32 + i];  // rot layout [f][h][i] (b bcast)
        }
        __syncthreads();

        u64 acc[16];
#pragma unroll
        for (int p = 0; p < 16; p++) acc[p] = 0ull;   // (0.0f, 0.0f)

        for (int f = 0; f < 64; f++) {
            u64 qb = pack2(q[f], q[f]);
            const ulonglong2* rr = (const ulonglong2*)&rot_s[f * 32]; // LDS.128 bcast
#pragma unroll
            for (int p2 = 0; p2 < 8; p2++) {
                ulonglong2 vv = rr[p2];
                acc[2 * p2 + 0] = ffma2(qb, vv.x, acc[2 * p2 + 0]);
                acc[2 * p2 + 1] = ffma2(qb, vv.y, acc[2 * p2 + 1]);
            }
        }

        float bestp = -1e30f, bestn = -1e30f;
        int ip = 0, inn = 0;
#pragma unroll
        for (int p = 0; p < 16; p++) {
            float2 a = unpack2(acc[p]);
            int i0 = 2 * p, i1 = 2 * p + 1;
            if ( a.x > bestp) { bestp =  a.x; ip  = i0; }
            if (-a.x > bestn) { bestn = -a.x; inn = i0; }
            if ( a.y > bestp) { bestp =  a.y; ip  = i1; }
            if (-a.y > bestn) { bestn = -a.y; inn = i1; }
        }
        int idx = (bestp >= bestn) ? ip : (32 + inn);  // plus-half wins ties
        g_bucket[((size_t)b * PH + h) * PS + t] = (unsigned char)idx;
        if (write_buckets)
            out_tail[((size_t)b * PH + h) * PS + t] = (float)(idx + h * PNB);
    }
}

// ---------------------------------------------------------------------------
// Kernel 2: stable counting sort per (b,h): 4096 tokens into 64 buckets by
// (bucket, t) — exactly jnp.argsort of S*bucket + t. grid: PB*PH, 128 threads.
// ---------------------------------------------------------------------------
__global__ void __launch_bounds__(128) k_sort()
{
    __shared__ unsigned char sb[4096];
    __shared__ int hist[64];
    __shared__ int offs[64];
    int bh = blockIdx.x;
    int tid = threadIdx.x;

    if (tid < 64) hist[tid] = 0;
    const unsigned int* src = (const unsigned int*)(g_bucket + (size_t)bh * PS);
    unsigned int* dstb = (unsigned int*)sb;
    for (int i = tid; i < 1024; i += 128) dstb[i] = src[i];
    __syncthreads();

    for (int t = tid; t < 4096; t += 128) atomicAdd(&hist[sb[t]], 1);
    __syncthreads();

    if (tid == 0) {
        int run = 0;
        for (int k = 0; k < 64; k++) { offs[k] = run; run += hist[k]; }
    }
    __syncthreads();

    if (tid < 64) {
        int k = tid;
        int pos = offs[k];
        int* dst = g_st + (size_t)bh * PS;
        for (int t = 0; t < 4096; t++)
            if (sb[t] == (unsigned char)k) dst[pos++] = t;  // stable: t ascending
    }
}

// ---------------------------------------------------------------------------
// Kernel 3: chunk attention, 128 thr/CTA, 4 CTAs/SM, conflict-free LDS.
//   QK^T: 8x8 tile; thread cols {4tx..4tx+3} u {64+4tx..+3} — contiguous
//   16B-per-lane LDS.128 (2-phase optimum). Softmax in registers (16-lane
//   shfl), exp values kept in acc regs across the barrier.
//   P (fp32, stride 132) aliases dead K^T region; V (fp16, stride 68 halves)
//   aliases dead Q region -> smem 51.9 KB -> 4 CTAs/SM (16 warps).
//   PV: rows ry+16*ii, d = 8*tx8..+7; V half2 cvt to f32x2 pairs.
// ---------------------------------------------------------------------------
#define SM_Q   (64 * 68)     // 4352 floats; aliased by V fp16 [128][68] halves
#define SM_KV  (64 * 132)    // 8448 floats; K^T [f][j], aliased by P [i][j]
#define SMEM3_FLOATS (SM_Q + SM_KV + 128 + 64)
#define SMEM3_BYTES  (SMEM3_FLOATS * 4)

__global__ void __launch_bounds__(128, 4) k_attn(
    const float* __restrict__ qk, const float* __restrict__ v)
{
    extern __shared__ float sm[];
    float*  q_s  = sm;                        // [i*68 + f] (phase 1)
    __half* v_h  = (__half*)sm;               // [j*68 + d] halves (phase 2)
    float*  kv_s = sm + SM_Q;                 // K^T [f*132 + j] (phase 1)
    float*  p_s  = kv_s;                      // P   [i*132 + j] (phase 2)
    int*    st_k = (int*)(sm + SM_Q + SM_KV); // 128 orig positions
    float*  s_inv = (float*)(st_k + 128);     // 64 per-row 1/sum

    int tid = threadIdx.x;
    int b = blockIdx.x >> 9;
    int c = blockIdx.x & 511;
    int h  = c >> 6;
    int cp = (c + 511) & 511;
    int hp = cp >> 6;

    if (tid < 64) {
        st_k[tid]      = g_st[((size_t)b * PH + h ) * PS + (c  & 63) * 64 + tid];
        st_k[64 + tid] = g_st[((size_t)b * PH + hp) * PS + (cp & 63) * 64 + tid];
    }
    __syncthreads();

    // ---- load Q (raw): threads 0-63 cover f 0..31, 64-127 cover f 32..63 --
    {
        int i  = tid & 63;
        int f0 = (tid >> 6) * 32;
        const float* row = qk + ((size_t)b * PS + st_k[i]) * PD + f0;
        float* dst = q_s + i * 68 + f0;
#pragma unroll
        for (int u = 0; u < 8; u++)
            ((float4*)dst)[u] = ((const float4*)row)[u];
    }
    // ---- load K: row-normalized (clip 1e-12), transposed, stride 132 ----
    {
        int j = tid;
        const float* row = qk + ((size_t)b * PS + st_k[j]) * PD;
        float r[64];
        float ss = 0.f;
#pragma unroll
        for (int u = 0; u < 16; u++) {
            float4 v4 = ((const float4*)row)[u];
            r[u * 4 + 0] = v4.x; r[u * 4 + 1] = v4.y;
            r[u * 4 + 2] = v4.z; r[u * 4 + 3] = v4.w;
            ss += v4.x * v4.x + v4.y * v4.y + v4.z * v4.z + v4.w * v4.w;
        }
        float inv = 1.0f / fmaxf(sqrtf(ss), 1e-12f);
#pragma unroll
        for (int f = 0; f < 64; f++) kv_s[f * 132 + j] = r[f] * inv;
    }
    __syncthreads();

    int ty = tid >> 4, tx = tid & 15;   // rows 8ty+ii; cols 4tx+u and 64+4tx+u
    u64 acc[8][4];                       // dots, then exp(P) bits after softmax

    // ---- dots = Q K^T (FFMA2, contiguous-lane LDS.128 for K) ----
    {
#pragma unroll
        for (int ii = 0; ii < 8; ii++)
#pragma unroll
            for (int g = 0; g < 4; g++) acc[ii][g] = 0ull;

        for (int kk0 = 0; kk0 < 64; kk0 += 4) {
            float4 qv[8];
#pragma unroll
            for (int ii = 0; ii < 8; ii++)
                qv[ii] = *(const float4*)&q_s[(8 * ty + ii) * 68 + kk0]; // LDS.128
#pragma unroll
            for (int u = 0; u < 4; u++) {
                int kk = kk0 + u;
                // 16 lanes x 16B contiguous -> 2-phase wavefront optimum
                ulonglong2 k0 = *(const ulonglong2*)&kv_s[kk * 132 + 4 * tx];      // cols 4tx..+3
                ulonglong2 k1 = *(const ulonglong2*)&kv_s[kk * 132 + 64 + 4 * tx]; // cols 64+4tx..+3
#pragma unroll
                for (int ii = 0; ii < 8; ii++) {
                    float qf = (u == 0) ? qv[ii].x : (u == 1) ? qv[ii].y
                             : (u == 2) ? qv[ii].z : qv[ii].w;
                    u64 qb = pack2(qf, qf);
                    acc[ii][0] = ffma2(qb, k0.x, acc[ii][0]);
                    acc[ii][1] = ffma2(qb, k0.y, acc[ii][1]);
                    acc[ii][2] = ffma2(qb, k1.x, acc[ii][2]);
                    acc[ii][3] = ffma2(qb, k1.y, acc[ii][3]);
                }
            }
        }

        // ---- scale + self-mask + register softmax (16-lane shfl rows) ----
        int tj0[4], tj1[4];
#pragma unroll
        for (int u = 0; u < 4; u++) {
            tj0[u] = st_k[4 * tx + u];
            tj1[u] = st_k[64 + 4 * tx + u];
        }
#pragma unroll
        for (int ii = 0; ii < 8; ii++) {
            int i = 8 * ty + ii;
            int ti = st_k[i];
            float2 p[4];
#pragma unroll
            for (int g = 0; g < 4; g++) p[g] = unpack2(acc[ii][g]);
            p[0].x *= 0.125f; p[0].y *= 0.125f;
            p[1].x *= 0.125f; p[1].y *= 0.125f;
            p[2].x *= 0.125f; p[2].y *= 0.125f;
            p[3].x *= 0.125f; p[3].y *= 0.125f;
            if (ti == tj0[0]) p[0].x = -1e5f;
            if (ti == tj0[1]) p[0].y = -1e5f;
            if (ti == tj0[2]) p[1].x = -1e5f;
            if (ti == tj0[3]) p[1].y = -1e5f;
            if (ti == tj1[0]) p[2].x = -1e5f;
            if (ti == tj1[1]) p[2].y = -1e5f;
            if (ti == tj1[2]) p[3].x = -1e5f;
            if (ti == tj1[3]) p[3].y = -1e5f;

            float m = fmaxf(fmaxf(fmaxf(p[0].x, p[0].y), fmaxf(p[1].x, p[1].y)),
                            fmaxf(fmaxf(p[2].x, p[2].y), fmaxf(p[3].x, p[3].y)));
            m = fmaxf(m, __shfl_xor_sync(0xffffffffu, m, 1));
            m = fmaxf(m, __shfl_xor_sync(0xffffffffu, m, 2));
            m = fmaxf(m, __shfl_xor_sync(0xffffffffu, m, 4));
            m = fmaxf(m, __shfl_xor_sync(0xffffffffu, m, 8));
            float s = 0.f;
#pragma unroll
            for (int g = 0; g < 4; g++) {
                p[g].x = __expf(p[g].x - m);
                p[g].y = __expf(p[g].y - m);
                s += p[g].x + p[g].y;
            }
            s += __shfl_xor_sync(0xffffffffu, s, 1);
            s += __shfl_xor_sync(0xffffffffu, s, 2);
            s += __shfl_xor_sync(0xffffffffu, s, 4);
            s += __shfl_xor_sync(0xffffffffu, s, 8);
            // keep exp values in acc registers across the barrier
#pragma unroll
            for (int g = 0; g < 4; g++) acc[ii][g] = pack2(p[g].x, p[g].y);
            if (tx == 0) {
                g_lse[((size_t)b * PH + h) * PS + ti] = m + __logf(s);
                s_inv[i] = 1.0f / s;
            }
        }
    }
    __syncthreads();   // all Q/K^T reads done -> both regions reusable

    // ---- write P (fp32) into old K^T region; V (fp16) into old Q region ---
    {
#pragma unroll
        for (int ii = 0; ii < 8; ii++) {
            int i = 8 * ty + ii;
            float2 a0 = unpack2(acc[ii][0]), a1 = unpack2(acc[ii][1]);
            float2 a2 = unpack2(acc[ii][2]), a3 = unpack2(acc[ii][3]);
            *(float4*)&p_s[i * 132 + 4 * tx]      = make_float4(a0.x, a0.y, a1.x, a1.y);
            *(float4*)&p_s[i * 132 + 64 + 4 * tx] = make_float4(a2.x, a2.y, a3.x, a3.y);
        }
        int j = tid;
        const float* row = v + ((size_t)b * PS + st_k[j]) * PD;
#pragma unroll
        for (int u = 0; u < 16; u++) {
            float4 v4 = ((const float4*)row)[u];
            __half2 h0 = __floats2half2_rn(v4.x, v4.y);
            __half2 h1 = __floats2half2_rn(v4.z, v4.w);
            *(uint2*)&v_h[j * 68 + 4 * u] =
                make_uint2(*(unsigned*)&h0, *(unsigned*)&h1);   // STS.64, 8B aligned
        }
    }
    __syncthreads();

    // ---- O = P V (FFMA2; rows ry+16ii, d = 8tx8..+7), scale, fp16 scatter --
    {
        int ry = tid >> 3, tx8 = tid & 7;
        int d0 = 8 * tx8;
        u64 oacc[4][4];
#pragma unroll
        for (int ii = 0; ii < 4; ii++)
#pragma unroll
            for (int g = 0; g < 4; g++) oacc[ii][g] = 0ull;

        for (int j0 = 0; j0 < 128; j0 += 4) {
            float4 pv4[4];
#pragma unroll
            for (int ii = 0; ii < 4; ii++)
                pv4[ii] = *(const float4*)&p_s[(ry + 16 * ii) * 132 + j0]; // LDS.128
#pragma unroll
            for (int u = 0; u < 4; u++) {
                int j = j0 + u;
                uint2 w0 = *(const uint2*)&v_h[j * 68 + d0];      // d0..d0+3 (4 halves)
                uint2 w1 = *(const uint2*)&v_h[j * 68 + d0 + 4];  // d0+4..d0+7
                float2 f0 = __half22float2(*(__half2*)&w0.x);
                float2 f1 = __half22float2(*(__half2*)&w0.y);
                float2 f2 = __half22float2(*(__half2*)&w1.x);
                float2 f3 = __half22float2(*(__half2*)&w1.y);
                u64 vp0 = pack2(f0.x, f0.y), vp1 = pack2(f1.x, f1.y);
                u64 vp2 = pack2(f2.x, f2.y), vp3 = pack2(f3.x, f3.y);
#pragma unroll
                for (int ii = 0; ii < 4; ii++) {
                    float pf = (u == 0) ? pv4[ii].x : (u == 1) ? pv4[ii].y
                             : (u == 2) ? pv4[ii].z : pv4[ii].w;
                    u64 pb = pack2(pf, pf);
                    oacc[ii][0] = ffma2(pb, vp0, oacc[ii][0]);
                    oacc[ii][1] = ffma2(pb, vp1, oacc[ii][1]);
                    oacc[ii][2] = ffma2(pb, vp2, oacc[ii][2]);
                    oacc[ii][3] = ffma2(pb, vp3, oacc[ii][3]);
                }
            }
        }
#pragma unroll
        for (int ii = 0; ii < 4; ii++) {
            int i = ry + 16 * ii;
            float inv = s_inv[i];
            size_t base = (((size_t)b * PH + h) * PS + st_k[i]) * (size_t)PD;
            __half2 hh[4];
#pragma unroll
            for (int g = 0; g < 4; g++) {
                float2 a = unpack2(oacc[ii][g]);
                hh[g] = __floats2half2_rn(a.x * inv, a.y * inv);
            }
            uint4 packed = make_uint4(*(unsigned*)&hh[0], *(unsigned*)&hh[1],
                                      *(unsigned*)&hh[2], *(unsigned*)&hh[3]);
            *(uint4*)&g_o[base + d0] = packed;   // STG.128, coalesced
        }
    }
}

// ---------------------------------------------------------------------------
// no-op launch: keeps the fixed ncu capture slot (our 4th launch) on k_attn
// ---------------------------------------------------------------------------
__global__ void k_nop() {}

// ---------------------------------------------------------------------------
// Kernel 4: combine hash rounds: w_h = exp(lse_h - logsumexp_h), out = sum w_h o_h.
// fp16 g_o read as half2 pairs; fp32 accumulate + output.
// ---------------------------------------------------------------------------
__global__ void __launch_bounds__(256) k_combine(float* __restrict__ out)
{
    __shared__ float sw[32 * 8];
    int b  = blockIdx.x >> 7;
    int t0 = (blockIdx.x & 127) * 32;
    int tid = threadIdx.x;
    int tl = tid >> 3, h = tid & 7;
    int t = t0 + tl;

    float l = g_lse[((size_t)b * PH + h) * PS + t];
    float m = l;
#pragma unroll
    for (int o = 4; o; o >>= 1) m = fmaxf(m, __shfl_xor_sync(0xffffffffu, m, o));
    float s = __expf(l - m);
#pragma unroll
    for (int o = 4; o; o >>= 1) s += __shfl_xor_sync(0xffffffffu, s, o);
    sw[tl * 8 + h] = __expf(l - (m + __logf(s)));
    __syncthreads();

    // 32 tokens x 32 d-pairs = 1024 pairs, 4 per thread
#pragma unroll
    for (int r = 0; r < 4; r++) {
        int idx = tid + r * 256;
        int tl2 = idx >> 5, dp = idx & 31;
        int t2 = t0 + tl2;
        float ax = 0.f, ay = 0.f;
#pragma unroll
        for (int hh = 0; hh < 8; hh++) {
            __half2 hv = *(const __half2*)
                &g_o[(((size_t)b * PH + hh) * PS + t2) * (size_t)PD + 2 * dp];
            float2 f = __half22float2(hv);
            float w = sw[tl2 * 8 + hh];
            ax += f.x * w; ay += f.y * w;
        }
        float2 res = make_float2(ax, ay);
        *(float2*)&out[((size_t)b * PS + t2) * (size_t)PD + 2 * dp] = res;
    }
}

// ---------------------------------------------------------------------------
extern "C" void kernel_launch(void* const* d_in, const int* in_sizes, int n_in,
                              void* d_out, int out_size)
{
    (void)n_in; (void)in_sizes;
    const float* qk  = (const float*)d_in[0];
    const float* v   = (const float*)d_in[1];
    const float* rot = (const float*)d_in[2];
    float* out = (float*)d_out;

    const int n_main = PB * PS * PD;            // 4194304
    const int n_buck = PB * PH * PS;            // 524288
    int write_buckets = (out_size >= n_main + n_buck) ? 1 : 0;

    cudaFuncSetAttribute(k_attn, cudaFuncAttributeMaxDynamicSharedMemorySize,
                         SMEM3_BYTES);

    k_hash<<<PB * (PS / 256), 256>>>(qk, rot, out + n_main, write_buckets);
    k_sort<<<PB * PH, 128>>>();
    k_nop<<<1, 32>>>();   // capture slot #4 (2 harness launches + these) = k_attn
    k_attn<<<PB * PCHUNKS, 128, SMEM3_BYTES>>>(qk, v);
    k_combine<<<PB * (PS / 32), 256>>>(out);
}